// round 2
// baseline (speedup 1.0000x reference)
#include <cuda_runtime.h>

// NeuralTMT — GB300 sm_103a
// Inputs (metadata order): IL[4,V,64] f32, LI[4,V,64] f32, UI[4,U,64] f32,
// IU[V,64] f32, alpha[4] f32, uid[B] i32, baskets[4,B,50] i32,
// iid[4,B] i32, neg_iid[4,B] i32. Output: f32[8*B] =
// (pos0, neg0, pos1, neg1, pos2, neg2, pos3, neg3).

#define TMT_V 100001
#define TMT_U 100000
#define TMT_K 64
#define TMT_B 16384
#define TMT_L 50
#define TMT_NEG_BIG (-4294967295.0f)   // -(2^32)+1

__global__ __launch_bounds__(256, 4)
void neuraltmt_kernel(const float* __restrict__ IL,
                      const float* __restrict__ LI,
                      const float* __restrict__ UI,
                      const float* __restrict__ IU,
                      const float* __restrict__ alpha,
                      const int*   __restrict__ uid,
                      const int*   __restrict__ baskets,
                      const int*   __restrict__ iid,
                      const int*   __restrict__ neg_iid,
                      float*       __restrict__ out)
{
    __shared__ int   sidx[4][TMT_L];
    __shared__ float xs[4][TMT_K];

    const int b = blockIdx.x;
    const int t = threadIdx.x;

    // ---------------- Phase 1: x[b,s,k] = mean_l LI[s, baskets[s,b,l], k] ---
    const int s = t >> 6;        // period 0..3
    const int k = t & 63;        // feature dim
    const int g = t & 63;        // index within 64-thread group

    if (g < TMT_L) {
        sidx[s][g] = baskets[((long long)s * TMT_B + b) * TMT_L + g];
    }
    __syncthreads();

    float acc = 0.0f;
    const float* LIs = LI + (long long)s * TMT_V * TMT_K + k;
    #pragma unroll
    for (int l = 0; l < TMT_L; ++l) {
        const int idx = sidx[s][l];          // broadcast LDS
        acc += __ldg(LIs + (long long)idx * TMT_K);
    }
    // Padding row of LI is zero, so masked-mean == sum/L.
    xs[s][k] = acc * (1.0f / (float)TMT_L);
    __syncthreads();

    // ---------------- Phase 2: per-warp (period, pos/neg) scoring -----------
    const int w    = t >> 5;      // warp 0..7
    const int p    = w >> 1;      // period
    const int neg  = w & 1;       // 0 = pos, 1 = neg
    const int lane = t & 31;

    const int item = (neg ? neg_iid : iid)[p * TMT_B + b];

    const float* tgt = IL + ((long long)p * TMT_V + item) * TMT_K;
    const float  t0  = tgt[lane];
    const float  t1  = tgt[lane + 32];

    float d0 = xs[0][lane] * t0 + xs[0][lane + 32] * t1;
    float d1 = xs[1][lane] * t0 + xs[1][lane + 32] * t1;
    float d2 = xs[2][lane] * t0 + xs[2][lane + 32] * t1;
    float d3 = xs[3][lane] * t0 + xs[3][lane + 32] * t1;

    const float* u  = UI + ((long long)p * TMT_U + uid[b]) * TMT_K;
    const float* iu = IU + (long long)item * TMT_K;
    float dm = u[lane] * iu[lane] + u[lane + 32] * iu[lane + 32];

    #pragma unroll
    for (int off = 16; off > 0; off >>= 1) {
        d0 += __shfl_xor_sync(0xffffffffu, d0, off);
        d1 += __shfl_xor_sync(0xffffffffu, d1, off);
        d2 += __shfl_xor_sync(0xffffffffu, d2, off);
        d3 += __shfl_xor_sync(0xffffffffu, d3, off);
        dm += __shfl_xor_sync(0xffffffffu, dm, off);
    }

    if (lane == 0) {
        float d[4] = {d0, d1, d2, d3};
        float wv[4];
        float mx = -3.402823466e38f;
        #pragma unroll
        for (int i = 0; i < 4; ++i) {
            float v = d[i] * 0.125f;              // / sqrt(64)
            if (v == 0.0f) v = TMT_NEG_BIG;       // mask exact zeros
            wv[i] = v;
            mx = fmaxf(mx, v);
        }
        float sum = 0.0f;
        #pragma unroll
        for (int i = 0; i < 4; ++i) { wv[i] = expf(wv[i] - mx); sum += wv[i]; }
        float attn = 0.0f;
        #pragma unroll
        for (int i = 0; i < 4; ++i) attn += wv[i] * d[i];
        attn /= sum;

        const float a  = alpha[p];
        const float sg = 1.0f / (1.0f + expf(-a));
        out[(2 * p + neg) * TMT_B + b] = sg * attn + (1.0f - sg) * dm;
    }
}

extern "C" void kernel_launch(void* const* d_in, const int* in_sizes, int n_in,
                              void* d_out, int out_size)
{
    const float* IL      = (const float*)d_in[0];
    const float* LI      = (const float*)d_in[1];
    const float* UI      = (const float*)d_in[2];
    const float* IU      = (const float*)d_in[3];
    const float* alpha   = (const float*)d_in[4];
    const int*   uid     = (const int*)  d_in[5];
    const int*   baskets = (const int*)  d_in[6];
    const int*   iid     = (const int*)  d_in[7];
    const int*   neg_iid = (const int*)  d_in[8];
    float*       out     = (float*)d_out;

    neuraltmt_kernel<<<TMT_B, 256>>>(IL, LI, UI, IU, alpha, uid, baskets,
                                     iid, neg_iid, out);
}

// round 5
// speedup vs baseline: 1.2656x; 1.2656x over previous
#include <cuda_runtime.h>

// NeuralTMT — GB300 sm_103a, round 3: float4-vectorized gathers, 4 batch
// elements per 256-thread CTA.
// Inputs (metadata order): IL[4,V,64] f32, LI[4,V,64] f32, UI[4,U,64] f32,
// IU[V,64] f32, alpha[4] f32, uid[B] i32, baskets[4,B,50] i32,
// iid[4,B] i32, neg_iid[4,B] i32. Output f32[8*B].

#define TMT_V 100001
#define TMT_U 100000
#define TMT_K 64
#define TMT_B 16384
#define TMT_L 50
#define TMT_NEG_BIG (-4294967295.0f)   // -(2^32)+1

__global__ __launch_bounds__(256, 4)
void neuraltmt_kernel(const float* __restrict__ IL,
                      const float* __restrict__ LI,
                      const float* __restrict__ UI,
                      const float* __restrict__ IU,
                      const float* __restrict__ alpha,
                      const int*   __restrict__ uid,
                      const int*   __restrict__ baskets,
                      const int*   __restrict__ iid,
                      const int*   __restrict__ neg_iid,
                      float*       __restrict__ out)
{
    __shared__ int   sidx[4][4][TMT_L];      // [b_local][period][l]
    __shared__ float xs[4][4][TMT_K];        // [b_local][period][k]

    const int t   = threadIdx.x;
    const int bl  = t >> 6;                  // b_local 0..3
    const int sub = t & 63;
    const int b   = blockIdx.x * 4 + bl;

    // ---- stage basket indices: 200 ints per b, 64 threads each ------------
    {
        const int* bb = baskets + (long long)b * TMT_L;   // + s*B*L per period
        #pragma unroll
        for (int i = sub; i < 4 * TMT_L; i += 64) {
            const int s = i / TMT_L;
            const int l = i - s * TMT_L;
            sidx[bl][s][l] = bb[(long long)s * TMT_B * TMT_L + l];
        }
    }
    __syncthreads();

    // ---- Phase 1: x[b,s,:] = mean_l LI[s, idx, :], float4 per thread ------
    {
        const int s = sub >> 4;              // period 0..3
        const int q = sub & 15;              // float4 slot 0..15 (k = 4q)
        const float4* LIs =
            (const float4*)(LI + (long long)s * TMT_V * TMT_K) + q;
        float4 acc = make_float4(0.f, 0.f, 0.f, 0.f);
        #pragma unroll
        for (int l = 0; l < TMT_L; ++l) {
            const int idx = sidx[bl][s][l];          // broadcast LDS
            const float4 v = __ldg(LIs + (long long)idx * (TMT_K / 4));
            acc.x += v.x; acc.y += v.y; acc.z += v.z; acc.w += v.w;
        }
        const float inv = 1.0f / (float)TMT_L;
        acc.x *= inv; acc.y *= inv; acc.z *= inv; acc.w *= inv;
        ((float4*)xs[bl][s])[q] = acc;
    }
    __syncthreads();

    // ---- Phase 2: 32 tasks (b_local, period, pos/neg), 4 per warp ---------
    const int w    = t >> 5;                 // warp 0..7
    const int lane = t & 31;

    #pragma unroll
    for (int iter = 0; iter < 4; ++iter) {
        const int task = w * 4 + iter;       // 0..31
        const int tb   = task >> 3;          // b_local
        const int p    = (task >> 1) & 3;    // period
        const int neg  = task & 1;
        const int gb   = blockIdx.x * 4 + tb;

        const int item = (neg ? neg_iid : iid)[p * TMT_B + gb];

        const float* tgt = IL + ((long long)p * TMT_V + item) * TMT_K;
        const float  t0  = __ldg(tgt + lane);
        const float  t1  = __ldg(tgt + lane + 32);

        float d0 = xs[tb][0][lane] * t0 + xs[tb][0][lane + 32] * t1;
        float d1 = xs[tb][1][lane] * t0 + xs[tb][1][lane + 32] * t1;
        float d2 = xs[tb][2][lane] * t0 + xs[tb][2][lane + 32] * t1;
        float d3 = xs[tb][3][lane] * t0 + xs[tb][3][lane + 32] * t1;

        const float* u  = UI + ((long long)p * TMT_U + __ldg(uid + gb)) * TMT_K;
        const float* iu = IU + (long long)item * TMT_K;
        float dm = __ldg(u + lane) * __ldg(iu + lane)
                 + __ldg(u + lane + 32) * __ldg(iu + lane + 32);

        #pragma unroll
        for (int off = 16; off > 0; off >>= 1) {
            d0 += __shfl_xor_sync(0xffffffffu, d0, off);
            d1 += __shfl_xor_sync(0xffffffffu, d1, off);
            d2 += __shfl_xor_sync(0xffffffffu, d2, off);
            d3 += __shfl_xor_sync(0xffffffffu, d3, off);
            dm += __shfl_xor_sync(0xffffffffu, dm, off);
        }

        if (lane == 0) {
            float d[4] = {d0, d1, d2, d3};
            float wv[4];
            float mx = -3.402823466e38f;
            #pragma unroll
            for (int i = 0; i < 4; ++i) {
                float v = d[i] * 0.125f;             // / sqrt(64)
                if (v == 0.0f) v = TMT_NEG_BIG;      // mask exact zeros
                wv[i] = v;
                mx = fmaxf(mx, v);
            }
            float sum = 0.0f;
            #pragma unroll
            for (int i = 0; i < 4; ++i) { wv[i] = expf(wv[i] - mx); sum += wv[i]; }
            float attn = 0.0f;
            #pragma unroll
            for (int i = 0; i < 4; ++i) attn += wv[i] * d[i];
            attn /= sum;

            const float a  = alpha[p];
            const float sg = 1.0f / (1.0f + expf(-a));
            out[(2 * p + neg) * TMT_B + gb] = sg * attn + (1.0f - sg) * dm;
        }
    }
}

extern "C" void kernel_launch(void* const* d_in, const int* in_sizes, int n_in,
                              void* d_out, int out_size)
{
    const float* IL      = (const float*)d_in[0];
    const float* LI      = (const float*)d_in[1];
    const float* UI      = (const float*)d_in[2];
    const float* IU      = (const float*)d_in[3];
    const float* alpha   = (const float*)d_in[4];
    const int*   uid     = (const int*)  d_in[5];
    const int*   baskets = (const int*)  d_in[6];
    const int*   iid     = (const int*)  d_in[7];
    const int*   neg_iid = (const int*)  d_in[8];
    float*       out     = (float*)d_out;

    neuraltmt_kernel<<<TMT_B / 4, 256>>>(IL, LI, UI, IU, alpha, uid, baskets,
                                         iid, neg_iid, out);
}

// round 6
// speedup vs baseline: 1.3288x; 1.0499x over previous
#include <cuda_runtime.h>

// NeuralTMT — GB300 sm_103a, round 5: two-kernel split.
// K1: period-major basket gather + mean into device scratch (LI slice stays
//     L2-resident per wave cohort; lean regs -> full occupancy).
// K2: attention + MF scoring (same math as previously-passing phase 2).
// Inputs (metadata order): IL[4,V,64] f32, LI[4,V,64] f32, UI[4,U,64] f32,
// IU[V,64] f32, alpha[4] f32, uid[B] i32, baskets[4,B,50] i32,
// iid[4,B] i32, neg_iid[4,B] i32. Output f32[8*B].

#define TMT_V 100001
#define TMT_U 100000
#define TMT_K 64
#define TMT_B 16384
#define TMT_L 50
#define TMT_NEG_BIG (-4294967295.0f)   // -(2^32)+1
#define K1_NB 16                        // batch elements per K1 CTA

// Scratch: x[b][period][k]  (16384 * 4 * 64 f32 = 16.8 MB)
__device__ float g_x[(long long)TMT_B * 4 * TMT_K];

// ---------------------------------------------------------------------------
// K1: x[b,p,:] = (1/L) * sum_l LI[p, baskets[p,b,l], :]
// grid = (B/16, 4), blockIdx.y = period (period-major dispatch order)
// ---------------------------------------------------------------------------
__global__ __launch_bounds__(256, 8)
void tmt_gather_kernel(const float* __restrict__ LI,
                       const int*   __restrict__ baskets)
{
    __shared__ int sidx[K1_NB * TMT_L];          // 800 ints

    const int p  = blockIdx.y;
    const int b0 = blockIdx.x * K1_NB;

    // Stage 800 contiguous basket indices for this (period, 16-b chunk).
    const int* bb = baskets + ((long long)p * TMT_B + b0) * TMT_L;
    #pragma unroll
    for (int i = threadIdx.x; i < K1_NB * TMT_L; i += 256)
        sidx[i] = bb[i];
    __syncthreads();

    const int bl = threadIdx.x >> 4;             // 0..15 local batch element
    const int q  = threadIdx.x & 15;             // float4 slot (k = 4q)

    const float4* LIs = (const float4*)(LI + (long long)p * TMT_V * TMT_K) + q;
    const int* idxp = sidx + bl * TMT_L;

    float4 acc = make_float4(0.f, 0.f, 0.f, 0.f);
    #pragma unroll
    for (int l = 0; l < TMT_L; ++l) {
        const int idx = idxp[l];                 // broadcast LDS
        const float4 v = __ldg(LIs + (long long)idx * (TMT_K / 4));
        acc.x += v.x; acc.y += v.y; acc.z += v.z; acc.w += v.w;
    }
    const float inv = 1.0f / (float)TMT_L;
    acc.x *= inv; acc.y *= inv; acc.z *= inv; acc.w *= inv;

    float4* xp = (float4*)(g_x + (((long long)(b0 + bl)) * 4 + p) * TMT_K) + q;
    *xp = acc;
}

// ---------------------------------------------------------------------------
// K2: per-warp (b_local, period, pos/neg) scoring; 4 b's per 256-thread CTA.
// ---------------------------------------------------------------------------
__global__ __launch_bounds__(256, 8)
void tmt_score_kernel(const float* __restrict__ IL,
                      const float* __restrict__ UI,
                      const float* __restrict__ IU,
                      const float* __restrict__ alpha,
                      const int*   __restrict__ uid,
                      const int*   __restrict__ iid,
                      const int*   __restrict__ neg_iid,
                      float*       __restrict__ out)
{
    __shared__ float xs[4][4][TMT_K];            // [b_local][period][k] = 4 KB

    const int t  = threadIdx.x;
    const int b0 = blockIdx.x * 4;

    // Stage x for this CTA's 4 batch elements (contiguous 4 KB in g_x).
    {
        const float4* src = (const float4*)(g_x + (long long)b0 * 4 * TMT_K);
        float4* dst = (float4*)&xs[0][0][0];
        #pragma unroll
        for (int i = t; i < 4 * 4 * TMT_K / 4; i += 256)
            dst[i] = src[i];
    }
    __syncthreads();

    const int w    = t >> 5;                     // warp 0..7
    const int lane = t & 31;

    #pragma unroll
    for (int iter = 0; iter < 4; ++iter) {
        const int task = w * 4 + iter;           // 0..31
        const int tb   = task >> 3;              // b_local
        const int p    = (task >> 1) & 3;        // period
        const int neg  = task & 1;
        const int gb   = b0 + tb;

        const int item = (neg ? neg_iid : iid)[p * TMT_B + gb];

        const float* tgt = IL + ((long long)p * TMT_V + item) * TMT_K;
        const float  t0  = __ldg(tgt + lane);
        const float  t1  = __ldg(tgt + lane + 32);

        float d0 = xs[tb][0][lane] * t0 + xs[tb][0][lane + 32] * t1;
        float d1 = xs[tb][1][lane] * t0 + xs[tb][1][lane + 32] * t1;
        float d2 = xs[tb][2][lane] * t0 + xs[tb][2][lane + 32] * t1;
        float d3 = xs[tb][3][lane] * t0 + xs[tb][3][lane + 32] * t1;

        const float* u  = UI + ((long long)p * TMT_U + __ldg(uid + gb)) * TMT_K;
        const float* iu = IU + (long long)item * TMT_K;
        float dm = __ldg(u + lane) * __ldg(iu + lane)
                 + __ldg(u + lane + 32) * __ldg(iu + lane + 32);

        #pragma unroll
        for (int off = 16; off > 0; off >>= 1) {
            d0 += __shfl_xor_sync(0xffffffffu, d0, off);
            d1 += __shfl_xor_sync(0xffffffffu, d1, off);
            d2 += __shfl_xor_sync(0xffffffffu, d2, off);
            d3 += __shfl_xor_sync(0xffffffffu, d3, off);
            dm += __shfl_xor_sync(0xffffffffu, dm, off);
        }

        if (lane == 0) {
            float d[4] = {d0, d1, d2, d3};
            float wv[4];
            float mx = -3.402823466e38f;
            #pragma unroll
            for (int i = 0; i < 4; ++i) {
                float v = d[i] * 0.125f;         // / sqrt(64)
                if (v == 0.0f) v = TMT_NEG_BIG;  // mask exact zeros
                wv[i] = v;
                mx = fmaxf(mx, v);
            }
            float sum = 0.0f;
            #pragma unroll
            for (int i = 0; i < 4; ++i) { wv[i] = expf(wv[i] - mx); sum += wv[i]; }
            float attn = 0.0f;
            #pragma unroll
            for (int i = 0; i < 4; ++i) attn += wv[i] * d[i];
            attn /= sum;

            const float a  = alpha[p];
            const float sg = 1.0f / (1.0f + expf(-a));
            out[(2 * p + neg) * TMT_B + gb] = sg * attn + (1.0f - sg) * dm;
        }
    }
}

extern "C" void kernel_launch(void* const* d_in, const int* in_sizes, int n_in,
                              void* d_out, int out_size)
{
    const float* IL      = (const float*)d_in[0];
    const float* LI      = (const float*)d_in[1];
    const float* UI      = (const float*)d_in[2];
    const float* IU      = (const float*)d_in[3];
    const float* alpha   = (const float*)d_in[4];
    const int*   uid     = (const int*)  d_in[5];
    const int*   baskets = (const int*)  d_in[6];
    const int*   iid     = (const int*)  d_in[7];
    const int*   neg_iid = (const int*)  d_in[8];
    float*       out     = (float*)d_out;

    dim3 g1(TMT_B / K1_NB, 4);
    tmt_gather_kernel<<<g1, 256>>>(LI, baskets);
    tmt_score_kernel<<<TMT_B / 4, 256>>>(IL, UI, IU, alpha, uid,
                                         iid, neg_iid, out);
}

// round 9
// speedup vs baseline: 1.5950x; 1.2004x over previous
#include <cuda_runtime.h>

// NeuralTMT — GB300 sm_103a, round 8 (resubmit of round-6 kernel; infra
// failure last round). K2 restructured to 8-lane sub-warp tasks
// (4 concurrent tasks per warp, 3-stage reductions).
// K1: period-major basket gather + mean into device scratch.
// Inputs (metadata order): IL[4,V,64] f32, LI[4,V,64] f32, UI[4,U,64] f32,
// IU[V,64] f32, alpha[4] f32, uid[B] i32, baskets[4,B,50] i32,
// iid[4,B] i32, neg_iid[4,B] i32. Output f32[8*B].

#define TMT_V 100001
#define TMT_U 100000
#define TMT_K 64
#define TMT_B 16384
#define TMT_L 50
#define TMT_NEG_BIG (-4294967295.0f)   // -(2^32)+1
#define K1_NB 16                        // batch elements per K1 CTA

// Scratch: x[b][period][k]  (16384 * 4 * 64 f32 = 16.8 MB)
__device__ float g_x[(long long)TMT_B * 4 * TMT_K];

__device__ __forceinline__ float dot4(float4 a, float4 b) {
    return a.x * b.x + a.y * b.y + a.z * b.z + a.w * b.w;
}

// ---------------------------------------------------------------------------
// K1: x[b,p,:] = (1/L) * sum_l LI[p, baskets[p,b,l], :]
// grid = (B/16, 4), blockIdx.y = period (period-major dispatch order)
// ---------------------------------------------------------------------------
__global__ __launch_bounds__(256, 8)
void tmt_gather_kernel(const float* __restrict__ LI,
                       const int*   __restrict__ baskets)
{
    __shared__ int sidx[K1_NB * TMT_L];          // 800 ints

    const int p  = blockIdx.y;
    const int b0 = blockIdx.x * K1_NB;

    const int* bb = baskets + ((long long)p * TMT_B + b0) * TMT_L;
    #pragma unroll
    for (int i = threadIdx.x; i < K1_NB * TMT_L; i += 256)
        sidx[i] = bb[i];
    __syncthreads();

    const int bl = threadIdx.x >> 4;             // 0..15 local batch element
    const int q  = threadIdx.x & 15;             // float4 slot (k = 4q)

    const float4* LIs = (const float4*)(LI + (long long)p * TMT_V * TMT_K) + q;
    const int* idxp = sidx + bl * TMT_L;

    float4 acc = make_float4(0.f, 0.f, 0.f, 0.f);
    #pragma unroll
    for (int l = 0; l < TMT_L; ++l) {
        const int idx = idxp[l];                 // broadcast LDS
        const float4 v = __ldg(LIs + (long long)idx * (TMT_K / 4));
        acc.x += v.x; acc.y += v.y; acc.z += v.z; acc.w += v.w;
    }
    const float inv = 1.0f / (float)TMT_L;
    acc.x *= inv; acc.y *= inv; acc.z *= inv; acc.w *= inv;

    float4* xp = (float4*)(g_x + (((long long)(b0 + bl)) * 4 + p) * TMT_K) + q;
    *xp = acc;
}

// ---------------------------------------------------------------------------
// K2: 8-lane sub-warp per (b_local, period, pos/neg) task.
// 256 threads = 8 warps = 32 groups = 32 tasks = 4 batch elements per CTA.
// ---------------------------------------------------------------------------
__global__ __launch_bounds__(256, 8)
void tmt_score_kernel(const float* __restrict__ IL,
                      const float* __restrict__ UI,
                      const float* __restrict__ IU,
                      const float* __restrict__ alpha,
                      const int*   __restrict__ uid,
                      const int*   __restrict__ iid,
                      const int*   __restrict__ neg_iid,
                      float*       __restrict__ out)
{
    __shared__ float xs[4][4][TMT_K];            // [b_local][period][k] = 4 KB

    const int t  = threadIdx.x;
    const int b0 = blockIdx.x * 4;

    // Stage x for this CTA's 4 batch elements (contiguous 4 KB in g_x).
    {
        const float4* src = (const float4*)(g_x + (long long)b0 * 4 * TMT_K);
        float4* dst = (float4*)&xs[0][0][0];
        #pragma unroll
        for (int i = t; i < 4 * 4 * TMT_K / 4; i += 256)
            dst[i] = src[i];
    }
    __syncthreads();

    const int w    = t >> 5;                     // warp 0..7
    const int lane = t & 31;
    const int g    = lane >> 3;                  // group 0..3 within warp
    const int kl   = lane & 7;                   // lane within group

    const int task = w * 4 + g;                  // 0..31
    const int bl   = task >> 3;                  // b_local
    const int p    = (task >> 1) & 3;            // period
    const int neg  = task & 1;
    const int gb   = b0 + bl;

    const int item = __ldg((neg ? neg_iid : iid) + p * TMT_B + gb);

    // Target row: two float4 per lane, coalesced 128 B per group request.
    const float4* tgt4 =
        (const float4*)(IL + ((long long)p * TMT_V + item) * TMT_K);
    const float4 ta = __ldg(tgt4 + kl);
    const float4 tc = __ldg(tgt4 + 8 + kl);

    // Partial dots over this lane's 8 k-elements.
    const float4* xs0 = (const float4*)xs[bl][0];
    const float4* xs1 = (const float4*)xs[bl][1];
    const float4* xs2 = (const float4*)xs[bl][2];
    const float4* xs3 = (const float4*)xs[bl][3];
    float d0 = dot4(xs0[kl], ta) + dot4(xs0[8 + kl], tc);
    float d1 = dot4(xs1[kl], ta) + dot4(xs1[8 + kl], tc);
    float d2 = dot4(xs2[kl], ta) + dot4(xs2[8 + kl], tc);
    float d3 = dot4(xs3[kl], ta) + dot4(xs3[8 + kl], tc);

    const float4* u4 =
        (const float4*)(UI + ((long long)p * TMT_U + __ldg(uid + gb)) * TMT_K);
    const float4* iu4 = (const float4*)(IU + (long long)item * TMT_K);
    float dm = dot4(__ldg(u4 + kl), __ldg(iu4 + kl))
             + dot4(__ldg(u4 + 8 + kl), __ldg(iu4 + 8 + kl));

    // 3-stage butterfly within each 8-lane group.
    #pragma unroll
    for (int off = 4; off > 0; off >>= 1) {
        d0 += __shfl_xor_sync(0xffffffffu, d0, off);
        d1 += __shfl_xor_sync(0xffffffffu, d1, off);
        d2 += __shfl_xor_sync(0xffffffffu, d2, off);
        d3 += __shfl_xor_sync(0xffffffffu, d3, off);
        dm += __shfl_xor_sync(0xffffffffu, dm, off);
    }

    if (kl == 0) {
        float d[4] = {d0, d1, d2, d3};
        float wv[4];
        float mx = -3.402823466e38f;
        #pragma unroll
        for (int i = 0; i < 4; ++i) {
            float v = d[i] * 0.125f;             // / sqrt(64)
            if (v == 0.0f) v = TMT_NEG_BIG;      // mask exact zeros
            wv[i] = v;
            mx = fmaxf(mx, v);
        }
        float sum = 0.0f;
        #pragma unroll
        for (int i = 0; i < 4; ++i) { wv[i] = expf(wv[i] - mx); sum += wv[i]; }
        float attn = 0.0f;
        #pragma unroll
        for (int i = 0; i < 4; ++i) attn += wv[i] * d[i];
        attn /= sum;

        const float a  = __ldg(alpha + p);
        const float sg = 1.0f / (1.0f + expf(-a));
        out[(2 * p + neg) * TMT_B + gb] = sg * attn + (1.0f - sg) * dm;
    }
}

extern "C" void kernel_launch(void* const* d_in, const int* in_sizes, int n_in,
                              void* d_out, int out_size)
{
    const float* IL      = (const float*)d_in[0];
    const float* LI      = (const float*)d_in[1];
    const float* UI      = (const float*)d_in[2];
    const float* IU      = (const float*)d_in[3];
    const float* alpha   = (const float*)d_in[4];
    const int*   uid     = (const int*)  d_in[5];
    const int*   baskets = (const int*)  d_in[6];
    const int*   iid     = (const int*)  d_in[7];
    const int*   neg_iid = (const int*)  d_in[8];
    float*       out     = (float*)d_out;

    dim3 g1(TMT_B / K1_NB, 4);
    tmt_gather_kernel<<<g1, 256>>>(LI, baskets);
    tmt_score_kernel<<<TMT_B / 4, 256>>>(IL, UI, IU, alpha, uid,
                                         iid, neg_iid, out);
}

// round 14
// speedup vs baseline: 1.7044x; 1.0685x over previous
#include <cuda_runtime.h>

// NeuralTMT — GB300 sm_103a, round 13 (resubmit of round-12; infra failed
// twice before it ran). K1: split-L gather (2 half-lanes per (b,p,q) slot,
// shfl-combined) for 2x MLP, with corrected strided smem staging.
// K2: 8-lane sub-warp tasks (unchanged, near its memory roofline).
// Inputs (metadata order): IL[4,V,64] f32, LI[4,V,64] f32, UI[4,U,64] f32,
// IU[V,64] f32, alpha[4] f32, uid[B] i32, baskets[4,B,50] i32,
// iid[4,B] i32, neg_iid[4,B] i32. Output f32[8*B].

#define TMT_V 100001
#define TMT_U 100000
#define TMT_K 64
#define TMT_B 16384
#define TMT_L 50
#define TMT_NEG_BIG (-4294967295.0f)   // -(2^32)+1
#define K1_NB 8                         // batch elements per K1 CTA

// Scratch: x[b][period][k]  (16384 * 4 * 64 f32 = 16.8 MB)
__device__ float g_x[(long long)TMT_B * 4 * TMT_K];

__device__ __forceinline__ float dot4(float4 a, float4 b) {
    return a.x * b.x + a.y * b.y + a.z * b.z + a.w * b.w;
}

// ---------------------------------------------------------------------------
// K1: x[b,p,:] = (1/L) * sum_l LI[p, baskets[p,b,l], :]
// grid = (B/8, 4), blockIdx.y = period (period-major dispatch order).
// Warp covers one b: lane = h*16 + q; h in {0,1} sums 25 basket rows each
// over float4 slot q; partials combined with shfl_xor(16).
// ---------------------------------------------------------------------------
__global__ __launch_bounds__(256, 8)
void tmt_gather_kernel(const float* __restrict__ LI,
                       const int*   __restrict__ baskets)
{
    __shared__ int sidx[K1_NB * TMT_L];          // 400 ints

    const int p  = blockIdx.y;
    const int b0 = blockIdx.x * K1_NB;
    const int t  = threadIdx.x;

    // Strided stage — 400 ints, 256 threads.
    const int* bb = baskets + ((long long)p * TMT_B + b0) * TMT_L;
    #pragma unroll
    for (int i = t; i < K1_NB * TMT_L; i += 256)
        sidx[i] = bb[i];
    __syncthreads();

    const int bl   = t >> 5;                     // 0..7 local batch element
    const int lane = t & 31;
    const int h    = lane >> 4;                  // half 0/1: 25 l's each
    const int q    = lane & 15;                  // float4 slot (k = 4q)

    const float4* LIs = (const float4*)(LI + (long long)p * TMT_V * TMT_K) + q;
    const int* idxp = sidx + bl * TMT_L + h * 25;

    float4 acc = make_float4(0.f, 0.f, 0.f, 0.f);
    #pragma unroll
    for (int l = 0; l < 25; ++l) {
        const int idx = idxp[l];                 // broadcast LDS
        const float4 v = __ldg(LIs + (long long)idx * (TMT_K / 4));
        acc.x += v.x; acc.y += v.y; acc.z += v.z; acc.w += v.w;
    }

    // Combine the two halves (lane ^ 16 has the same (bl, q)).
    acc.x += __shfl_xor_sync(0xffffffffu, acc.x, 16);
    acc.y += __shfl_xor_sync(0xffffffffu, acc.y, 16);
    acc.z += __shfl_xor_sync(0xffffffffu, acc.z, 16);
    acc.w += __shfl_xor_sync(0xffffffffu, acc.w, 16);

    if (h == 0) {
        const float inv = 1.0f / (float)TMT_L;
        acc.x *= inv; acc.y *= inv; acc.z *= inv; acc.w *= inv;
        float4* xp =
            (float4*)(g_x + (((long long)(b0 + bl)) * 4 + p) * TMT_K) + q;
        *xp = acc;
    }
}

// ---------------------------------------------------------------------------
// K2: 8-lane sub-warp per (b_local, period, pos/neg) task.
// 256 threads = 8 warps = 32 groups = 32 tasks = 4 batch elements per CTA.
// ---------------------------------------------------------------------------
__global__ __launch_bounds__(256, 8)
void tmt_score_kernel(const float* __restrict__ IL,
                      const float* __restrict__ UI,
                      const float* __restrict__ IU,
                      const float* __restrict__ alpha,
                      const int*   __restrict__ uid,
                      const int*   __restrict__ iid,
                      const int*   __restrict__ neg_iid,
                      float*       __restrict__ out)
{
    __shared__ float xs[4][4][TMT_K];            // [b_local][period][k] = 4 KB

    const int t  = threadIdx.x;
    const int b0 = blockIdx.x * 4;

    // Stage x for this CTA's 4 batch elements (contiguous 4 KB in g_x).
    {
        const float4* src = (const float4*)(g_x + (long long)b0 * 4 * TMT_K);
        float4* dst = (float4*)&xs[0][0][0];
        #pragma unroll
        for (int i = t; i < 4 * 4 * TMT_K / 4; i += 256)
            dst[i] = src[i];
    }
    __syncthreads();

    const int w    = t >> 5;                     // warp 0..7
    const int lane = t & 31;
    const int g    = lane >> 3;                  // group 0..3 within warp
    const int kl   = lane & 7;                   // lane within group

    const int task = w * 4 + g;                  // 0..31
    const int bl   = task >> 3;                  // b_local
    const int p    = (task >> 1) & 3;            // period
    const int neg  = task & 1;
    const int gb   = b0 + bl;

    const int item = __ldg((neg ? neg_iid : iid) + p * TMT_B + gb);

    // Target row: two float4 per lane, coalesced 128 B per group request.
    const float4* tgt4 =
        (const float4*)(IL + ((long long)p * TMT_V + item) * TMT_K);
    const float4 ta = __ldg(tgt4 + kl);
    const float4 tc = __ldg(tgt4 + 8 + kl);

    // Partial dots over this lane's 8 k-elements.
    const float4* xs0 = (const float4*)xs[bl][0];
    const float4* xs1 = (const float4*)xs[bl][1];
    const float4* xs2 = (const float4*)xs[bl][2];
    const float4* xs3 = (const float4*)xs[bl][3];
    float d0 = dot4(xs0[kl], ta) + dot4(xs0[8 + kl], tc);
    float d1 = dot4(xs1[kl], ta) + dot4(xs1[8 + kl], tc);
    float d2 = dot4(xs2[kl], ta) + dot4(xs2[8 + kl], tc);
    float d3 = dot4(xs3[kl], ta) + dot4(xs3[8 + kl], tc);

    const float4* u4 =
        (const float4*)(UI + ((long long)p * TMT_U + __ldg(uid + gb)) * TMT_K);
    const float4* iu4 = (const float4*)(IU + (long long)item * TMT_K);
    float dm = dot4(__ldg(u4 + kl), __ldg(iu4 + kl))
             + dot4(__ldg(u4 + 8 + kl), __ldg(iu4 + 8 + kl));

    // 3-stage butterfly within each 8-lane group.
    #pragma unroll
    for (int off = 4; off > 0; off >>= 1) {
        d0 += __shfl_xor_sync(0xffffffffu, d0, off);
        d1 += __shfl_xor_sync(0xffffffffu, d1, off);
        d2 += __shfl_xor_sync(0xffffffffu, d2, off);
        d3 += __shfl_xor_sync(0xffffffffu, d3, off);
        dm += __shfl_xor_sync(0xffffffffu, dm, off);
    }

    if (kl == 0) {
        float d[4] = {d0, d1, d2, d3};
        float wv[4];
        float mx = -3.402823466e38f;
        #pragma unroll
        for (int i = 0; i < 4; ++i) {
            float v = d[i] * 0.125f;             // / sqrt(64)
            if (v == 0.0f) v = TMT_NEG_BIG;      // mask exact zeros
            wv[i] = v;
            mx = fmaxf(mx, v);
        }
        float sum = 0.0f;
        #pragma unroll
        for (int i = 0; i < 4; ++i) { wv[i] = expf(wv[i] - mx); sum += wv[i]; }
        float attn = 0.0f;
        #pragma unroll
        for (int i = 0; i < 4; ++i) attn += wv[i] * d[i];
        attn /= sum;

        const float a  = __ldg(alpha + p);
        const float sg = 1.0f / (1.0f + expf(-a));
        out[(2 * p + neg) * TMT_B + gb] = sg * attn + (1.0f - sg) * dm;
    }
}

extern "C" void kernel_launch(void* const* d_in, const int* in_sizes, int n_in,
                              void* d_out, int out_size)
{
    const float* IL      = (const float*)d_in[0];
    const float* LI      = (const float*)d_in[1];
    const float* UI      = (const float*)d_in[2];
    const float* IU      = (const float*)d_in[3];
    const float* alpha   = (const float*)d_in[4];
    const int*   uid     = (const int*)  d_in[5];
    const int*   baskets = (const int*)  d_in[6];
    const int*   iid     = (const int*)  d_in[7];
    const int*   neg_iid = (const int*)  d_in[8];
    float*       out     = (float*)d_out;

    dim3 g1(TMT_B / K1_NB, 4);
    tmt_gather_kernel<<<g1, 256>>>(LI, baskets);
    tmt_score_kernel<<<TMT_B / 4, 256>>>(IL, UI, IU, alpha, uid,
                                         iid, neg_iid, out);
}